// round 16
// baseline (speedup 1.0000x reference)
#include <cuda_runtime.h>
#include <cuda_bf16.h>
#include <cstdint>

#define M_TOT   8192
#define DM      1024
#define N_HEADS 16
#define HD      64
#define SEQ     2048

// bf16 2-plane buffers (device globals: no allocation in kernel_launch)
__device__ __nv_bfloat16 g_xb0[M_TOT * DM], g_xb1[M_TOT * DM];
__device__ __nv_bfloat16 g_Wb0[4 * DM * DM], g_Wb1[4 * DM * DM];
__device__ __nv_bfloat16 g_Qb0[M_TOT * DM], g_Qb1[M_TOT * DM];   // prescaled by 1/8
__device__ __nv_bfloat16 g_Kb0[M_TOT * DM], g_Kb1[M_TOT * DM];
__device__ __nv_bfloat16 g_Vb0[M_TOT * DM], g_Vb1[M_TOT * DM];
__device__ __nv_bfloat16 g_Ab0[M_TOT * DM], g_Ab1[M_TOT * DM];

// ---------------------------------------------------------------------------
// helpers
// ---------------------------------------------------------------------------
__device__ __forceinline__ void mma_bf16(float* d, const uint32_t* a, const uint32_t* b) {
    asm volatile(
        "mma.sync.aligned.m16n8k16.row.col.f32.bf16.bf16.f32 "
        "{%0,%1,%2,%3}, {%4,%5,%6,%7}, {%8,%9}, {%0,%1,%2,%3};"
        : "+f"(d[0]), "+f"(d[1]), "+f"(d[2]), "+f"(d[3])
        : "r"(a[0]), "r"(a[1]), "r"(a[2]), "r"(a[3]), "r"(b[0]), "r"(b[1]));
}

__device__ __forceinline__ uint32_t smem_addr_u32(const void* p) {
    uint32_t a;
    asm("{ .reg .u64 t; cvta.to.shared.u64 t, %1; cvt.u32.u64 %0, t; }" : "=r"(a) : "l"(p));
    return a;
}

__device__ __forceinline__ void cp16(uint32_t dst, const void* src) {
    asm volatile("cp.async.cg.shared.global [%0], [%1], 16;" :: "r"(dst), "l"(src));
}

// split a,b -> packed bf16 hi pair + lo (residual) pair
__device__ __forceinline__ void split_pack(float a, float b, uint32_t& h, uint32_t& l) {
    __nv_bfloat16 ha = __float2bfloat16(a), hb = __float2bfloat16(b);
    __nv_bfloat16 la = __float2bfloat16(a - __bfloat162float(ha));
    __nv_bfloat16 lb = __float2bfloat16(b - __bfloat162float(hb));
    h = (uint32_t)__bfloat16_as_ushort(ha) | ((uint32_t)__bfloat16_as_ushort(hb) << 16);
    l = (uint32_t)__bfloat16_as_ushort(la) | ((uint32_t)__bfloat16_as_ushort(lb) << 16);
}

// ---------------------------------------------------------------------------
// split: fp32 -> 2 bf16 planes (hi + exact residual)
// ---------------------------------------------------------------------------
__global__ __launch_bounds__(256) void split2_kernel(
    const float* __restrict__ src,
    __nv_bfloat16* __restrict__ p0, __nv_bfloat16* __restrict__ p1, int n)
{
    int i0 = (blockIdx.x * blockDim.x + threadIdx.x) * 8;
    int stride = gridDim.x * blockDim.x * 8;
    for (int i = i0; i < n; i += stride) {
        float4 va = *(const float4*)(src + i);
        float4 vb = *(const float4*)(src + i + 4);
        float v[8] = {va.x, va.y, va.z, va.w, vb.x, vb.y, vb.z, vb.w};
        uint32_t u0[4], u1[4];
#pragma unroll
        for (int e = 0; e < 4; e++)
            split_pack(v[2 * e], v[2 * e + 1], u0[e], u1[e]);
        *(uint4*)(p0 + i) = make_uint4(u0[0], u0[1], u0[2], u0[3]);
        *(uint4*)(p1 + i) = make_uint4(u1[0], u1[1], u1[2], u1[3]);
    }
}

// weights variant: grid.z selects which of the 4 matrices (one launch total)
__global__ __launch_bounds__(256) void split2w_kernel(
    const float* __restrict__ W0, const float* __restrict__ W1,
    const float* __restrict__ W2, const float* __restrict__ W3,
    __nv_bfloat16* __restrict__ p0, __nv_bfloat16* __restrict__ p1)
{
    const int z = blockIdx.z;
    const float* src = (z == 0) ? W0 : (z == 1) ? W1 : (z == 2) ? W2 : W3;
    __nv_bfloat16* d0 = p0 + (size_t)z * DM * DM;
    __nv_bfloat16* d1 = p1 + (size_t)z * DM * DM;
    int i0 = (blockIdx.x * blockDim.x + threadIdx.x) * 8;
    int stride = gridDim.x * blockDim.x * 8;
    for (int i = i0; i < DM * DM; i += stride) {
        float4 va = *(const float4*)(src + i);
        float4 vb = *(const float4*)(src + i + 4);
        float v[8] = {va.x, va.y, va.z, va.w, vb.x, vb.y, vb.z, vb.w};
        uint32_t u0[4], u1[4];
#pragma unroll
        for (int e = 0; e < 4; e++)
            split_pack(v[2 * e], v[2 * e + 1], u0[e], u1[e]);
        *(uint4*)(d0 + i) = make_uint4(u0[0], u0[1], u0[2], u0[3]);
        *(uint4*)(d1 + i) = make_uint4(u1[0], u1[1], u1[2], u1[3]);
    }
}

// ---------------------------------------------------------------------------
// GEMM v5 (byte-identical to the R15 winner): 3-pass 2-plane bf16 m16n8k16,
// 128x128 tile, plane-emitting epilogue.
// ---------------------------------------------------------------------------
#define GBM 128
#define GBN 128
#define GBK 32
#define SAB 40
#define APLANE_B (128 * SAB * 2)
#define BPLANE_B (128 * SAB * 2)
#define STAGE_B (2 * APLANE_B + 2 * BPLANE_B)
#define GEMM_SMEM (2 * STAGE_B)

__global__ __launch_bounds__(256) void gemm_bf16_kernel(
    const __nv_bfloat16* __restrict__ A0, const __nv_bfloat16* __restrict__ A1,
    const __nv_bfloat16* __restrict__ Wp0, const __nv_bfloat16* __restrict__ Wp1,
    int wslice_base, int plane_mode,
    const float* __restrict__ b0, const float* __restrict__ b1, const float* __restrict__ b2,
    float* __restrict__ Cf,
    __nv_bfloat16* __restrict__ Pq0, __nv_bfloat16* __restrict__ Pq1,
    __nv_bfloat16* __restrict__ Pk0, __nv_bfloat16* __restrict__ Pk1,
    __nv_bfloat16* __restrict__ Pv0, __nv_bfloat16* __restrict__ Pv1)
{
    extern __shared__ char smraw[];
    const uint32_t sb = smem_addr_u32(smraw);

    const int z = blockIdx.z;
    const size_t wofs = (size_t)(wslice_base + z) * DM * DM;
    const __nv_bfloat16* W0 = Wp0 + wofs;
    const __nv_bfloat16* W1 = Wp1 + wofs;
    const float* bias = (z == 0) ? b0 : (z == 1) ? b1 : b2;

    const int t    = threadIdx.x;
    const int lane = t & 31;
    const int warp = t >> 5;
    const int wm   = warp >> 1;
    const int wn   = warp & 1;
    const int bm   = blockIdx.x * GBM;
    const int bn   = blockIdx.y * GBN;
    const int g    = lane >> 2;
    const int tig  = lane & 3;

    float acc[2][8][4];
#pragma unroll
    for (int i = 0; i < 2; i++)
#pragma unroll
        for (int j = 0; j < 8; j++)
#pragma unroll
            for (int c = 0; c < 4; c++) acc[i][j][c] = 0.f;

    auto copy_stage = [&](int buf, int k0) {
        uint32_t tb = sb + (uint32_t)buf * STAGE_B;
#pragma unroll
        for (int i = 0; i < 8; i++) {
            int idx = t + i * 256;
            if (idx < 1024) {
                int p = idx >> 9;
                int r = (idx >> 2) & 127;
                int c = idx & 3;
                const __nv_bfloat16* gp = (p == 0) ? A0 : A1;
                cp16(tb + (uint32_t)p * APLANE_B + (uint32_t)(r * 80 + c * 16),
                     gp + (size_t)(bm + r) * DM + k0 + c * 8);
            } else {
                int idx2 = idx - 1024;
                int p = idx2 >> 9;
                int r = (idx2 >> 2) & 127;
                int c = idx2 & 3;
                const __nv_bfloat16* gp = (p == 0) ? W0 : W1;
                cp16(tb + 2u * APLANE_B + (uint32_t)p * BPLANE_B + (uint32_t)(r * 80 + c * 16),
                     gp + (size_t)(bn + r) * DM + k0 + c * 8);
            }
        }
        asm volatile("cp.async.commit_group;" ::: "memory");
    };

    auto compute_stage = [&](int buf) {
        const __nv_bfloat16* sAh = (const __nv_bfloat16*)(smraw + buf * STAGE_B);
        const __nv_bfloat16* sAl = sAh + 128 * SAB;
        const __nv_bfloat16* sBh = sAl + 128 * SAB;
        const __nv_bfloat16* sBl = sBh + 128 * SAB;
#pragma unroll
        for (int ks = 0; ks < 2; ks++) {
            const int kc = ks * 16 + 2 * tig;
            uint32_t ah[2][4], al[2][4];
#pragma unroll
            for (int i = 0; i < 2; i++) {
                int r0 = (wm * 32 + i * 16 + g) * SAB + kc;
                ah[i][0] = *(const uint32_t*)(sAh + r0);
                ah[i][1] = *(const uint32_t*)(sAh + r0 + 8 * SAB);
                ah[i][2] = *(const uint32_t*)(sAh + r0 + 8);
                ah[i][3] = *(const uint32_t*)(sAh + r0 + 8 * SAB + 8);
                al[i][0] = *(const uint32_t*)(sAl + r0);
                al[i][1] = *(const uint32_t*)(sAl + r0 + 8 * SAB);
                al[i][2] = *(const uint32_t*)(sAl + r0 + 8);
                al[i][3] = *(const uint32_t*)(sAl + r0 + 8 * SAB + 8);
            }
            uint32_t bhf[8][2], blf[8][2];
#pragma unroll
            for (int j = 0; j < 8; j++) {
                int n0 = (wn * 64 + j * 8 + g) * SAB + kc;
                bhf[j][0] = *(const uint32_t*)(sBh + n0);
                bhf[j][1] = *(const uint32_t*)(sBh + n0 + 8);
                blf[j][0] = *(const uint32_t*)(sBl + n0);
                blf[j][1] = *(const uint32_t*)(sBl + n0 + 8);
            }
#pragma unroll
            for (int i = 0; i < 2; i++)
#pragma unroll
                for (int j = 0; j < 8; j++)
                    mma_bf16(acc[i][j], ah[i], bhf[j]);
#pragma unroll
            for (int i = 0; i < 2; i++)
#pragma unroll
                for (int j = 0; j < 8; j++)
                    mma_bf16(acc[i][j], ah[i], blf[j]);
#pragma unroll
            for (int i = 0; i < 2; i++)
#pragma unroll
                for (int j = 0; j < 8; j++)
                    mma_bf16(acc[i][j], al[i], bhf[j]);
        }
    };

    copy_stage(0, 0);
    const int NS = DM / GBK;
    for (int s = 0; s < NS; s++) {
        asm volatile("cp.async.wait_group 0;" ::: "memory");
        __syncthreads();
        if (s + 1 < NS) copy_stage((s + 1) & 1, (s + 1) * GBK);
        compute_stage(s & 1);
    }

    if (plane_mode) {
        const float scale = (z == 0) ? 0.125f : 1.0f;
        __nv_bfloat16* P0 = (z == 0) ? Pq0 : (z == 1) ? Pk0 : Pv0;
        __nv_bfloat16* P1 = (z == 0) ? Pq1 : (z == 1) ? Pk1 : Pv1;
#pragma unroll
        for (int i = 0; i < 2; i++) {
#pragma unroll
            for (int j = 0; j < 8; j++) {
                int row0 = bm + wm * 32 + i * 16 + g;
                int col  = bn + wn * 64 + j * 8 + tig * 2;
                float bvx = bias[col], bvy = bias[col + 1];
                uint32_t h, l;
                split_pack((acc[i][j][0] + bvx) * scale, (acc[i][j][1] + bvy) * scale, h, l);
                *(uint32_t*)(P0 + (size_t)row0 * DM + col) = h;
                *(uint32_t*)(P1 + (size_t)row0 * DM + col) = l;
                split_pack((acc[i][j][2] + bvx) * scale, (acc[i][j][3] + bvy) * scale, h, l);
                *(uint32_t*)(P0 + (size_t)(row0 + 8) * DM + col) = h;
                *(uint32_t*)(P1 + (size_t)(row0 + 8) * DM + col) = l;
            }
        }
    } else {
#pragma unroll
        for (int i = 0; i < 2; i++) {
#pragma unroll
            for (int j = 0; j < 8; j++) {
                int row0 = bm + wm * 32 + i * 16 + g;
                int col  = bn + wn * 64 + j * 8 + tig * 2;
                float bvx = bias[col], bvy = bias[col + 1];
                float2 o0 = {acc[i][j][0] + bvx, acc[i][j][1] + bvy};
                float2 o1 = {acc[i][j][2] + bvx, acc[i][j][3] + bvy};
                *(float2*)(Cf + (size_t)row0 * DM + col)       = o0;
                *(float2*)(Cf + (size_t)(row0 + 8) * DM + col) = o1;
            }
        }
    }
}

// ---------------------------------------------------------------------------
// Flash attention v6 (causal): v5 compute core + software-pipelined tile loop.
// K double-buffered via cp.async (prefetch jt+1 during compute of jt);
// V prefetched into registers one tile ahead, STS-transposed at the top of
// the iteration. ONE __syncthreads per tile.
// smem: Qhi/Qlo[128][72] | {Khi,Klo}[2][64][72] | {Vhi,Vlo}[2][64][72] |
//       Phi/Plo[128][72]  = 147456 B
// ---------------------------------------------------------------------------
#define QST 72
#define OFS_QHI 0
#define OFS_QLO (128 * QST)
#define OFS_K0  (2 * 128 * QST)
#define KBUF_SZ (2 * 64 * QST)            // KHI + KLO per buffer
#define OFS_V0  (OFS_K0 + 2 * KBUF_SZ)
#define VBUF_SZ (2 * 64 * QST)
#define OFS_PHI (OFS_V0 + 2 * VBUF_SZ)
#define OFS_PLO (OFS_PHI + 128 * QST)
#define ATTN_SMEM ((OFS_PLO + 128 * QST) * 2)   // 147456 B

__global__ __launch_bounds__(256) void attn_kernel()
{
    extern __shared__ __nv_bfloat16 sm[];
    const __nv_bfloat16* Qhi = sm + OFS_QHI;
    const __nv_bfloat16* Qlo = sm + OFS_QLO;
    __nv_bfloat16* Phi = sm + OFS_PHI;
    __nv_bfloat16* Plo = sm + OFS_PLO;

    const uint32_t sb = smem_addr_u32(sm);

    const int t    = threadIdx.x;
    const int lane = t & 31;
    const int w    = t >> 5;
    const int g    = lane >> 2;
    const int tig  = lane & 3;
    const int qt   = 15 - (int)blockIdx.x;
    const int bh   = blockIdx.y;
    const int b    = bh >> 4;
    const int h    = bh & 15;

    const size_t base = (size_t)b * SEQ * DM + (size_t)h * HD;

    // Q planes via cp.async
#pragma unroll
    for (int i = 0; i < 8; i++) {
        int idx = t + i * 256;
        int p   = idx >> 10;
        int r   = (idx >> 3) & 127;
        int ch  = idx & 7;
        const __nv_bfloat16* gp = p ? g_Qb1 : g_Qb0;
        cp16(sb + (uint32_t)((p ? OFS_QLO : OFS_QHI) + r * QST + ch * 8) * 2u,
             gp + base + (size_t)(qt * 128 + r) * DM + ch * 8);
    }

    // ---- pipeline helpers ----
    auto load_K = [&](int jt, int buf) {
#pragma unroll
        for (int i = 0; i < 4; i++) {
            int idx = t + i * 256;
            int p   = idx >> 9;
            int r   = (idx >> 3) & 63;
            int ch  = idx & 7;
            const __nv_bfloat16* gp = p ? g_Kb1 : g_Kb0;
            cp16(sb + (uint32_t)(OFS_K0 + buf * KBUF_SZ + p * 64 * QST + r * QST + ch * 8) * 2u,
                 gp + base + (size_t)(jt * 64 + r) * DM + ch * 8);
        }
        asm volatile("cp.async.commit_group;" ::: "memory");
    };

    const int vrow = t & 63;
    const int vcg  = (t >> 6) << 4;
    uint4 vr0[2], vr1[2];
    auto fetch_V = [&](int jt) {
#pragma unroll
        for (int i = 0; i < 2; i++) {
            vr0[i] = *(const uint4*)(g_Vb0 + base + (size_t)(jt * 64 + vrow) * DM + vcg + i * 8);
            vr1[i] = *(const uint4*)(g_Vb1 + base + (size_t)(jt * 64 + vrow) * DM + vcg + i * 8);
        }
    };
    auto sts_V = [&](int buf) {
        __nv_bfloat16* Vh = sm + OFS_V0 + buf * VBUF_SZ;
        __nv_bfloat16* Vl = Vh + 64 * QST;
#pragma unroll
        for (int i = 0; i < 2; i++) {
            const __nv_bfloat16* e0 = (const __nv_bfloat16*)&vr0[i];
            const __nv_bfloat16* e1 = (const __nv_bfloat16*)&vr1[i];
#pragma unroll
            for (int e = 0; e < 8; e++) {
                Vh[(vcg + i * 8 + e) * QST + vrow] = e0[e];
                Vl[(vcg + i * 8 + e) * QST + vrow] = e1[e];
            }
        }
    };

    float Oacc[8][4];
    float rmax[2], rsum[2];
#pragma unroll
    for (int j = 0; j < 8; j++)
#pragma unroll
        for (int c = 0; c < 4; c++) Oacc[j][c] = 0.f;
    rmax[0] = rmax[1] = -1e30f;
    rsum[0] = rsum[1] = 0.f;

    const int nj = 2 * qt + 2;

    // prologue: K tile 0 (same cp.async groups as Q), V tile 0 into regs
    load_K(0, 0);
    fetch_V(0);

    for (int jt = 0; jt < nj; jt++) {
        const int cur = jt & 1;
        asm volatile("cp.async.wait_group 0;" ::: "memory");   // Q (jt=0) + K cur landed
        sts_V(cur);                                            // V tile jt -> smem
        __syncthreads();

        if (jt + 1 < nj) {
            load_K(jt + 1, 1 - cur);
            fetch_V(jt + 1);
        }

        const __nv_bfloat16* Khi = sm + OFS_K0 + cur * KBUF_SZ;
        const __nv_bfloat16* Klo = Khi + 64 * QST;
        const __nv_bfloat16* Vhi = sm + OFS_V0 + cur * VBUF_SZ;
        const __nv_bfloat16* Vlo = Vhi + 64 * QST;

        // ---- S = Q @ K^T (3-pass 2-plane bf16, k16) ----
        float Sacc[8][4];
#pragma unroll
        for (int j = 0; j < 8; j++)
#pragma unroll
            for (int c = 0; c < 4; c++) Sacc[j][c] = 0.f;

#pragma unroll
        for (int kf = 0; kf < 4; kf++) {
            const int kc = kf * 16 + 2 * tig;
            int ab = (w * 16 + g) * QST + kc;
            uint32_t ah[4], al[4];
            ah[0] = *(const uint32_t*)(Qhi + ab);
            ah[1] = *(const uint32_t*)(Qhi + ab + 8 * QST);
            ah[2] = *(const uint32_t*)(Qhi + ab + 8);
            ah[3] = *(const uint32_t*)(Qhi + ab + 8 * QST + 8);
            al[0] = *(const uint32_t*)(Qlo + ab);
            al[1] = *(const uint32_t*)(Qlo + ab + 8 * QST);
            al[2] = *(const uint32_t*)(Qlo + ab + 8);
            al[3] = *(const uint32_t*)(Qlo + ab + 8 * QST + 8);
#pragma unroll
            for (int j = 0; j < 8; j++) {
                int bb = (j * 8 + g) * QST + kc;
                uint32_t bhf[2] = {*(const uint32_t*)(Khi + bb), *(const uint32_t*)(Khi + bb + 8)};
                uint32_t blf[2] = {*(const uint32_t*)(Klo + bb), *(const uint32_t*)(Klo + bb + 8)};
                mma_bf16(Sacc[j], ah, bhf);
                mma_bf16(Sacc[j], ah, blf);
                mma_bf16(Sacc[j], al, bhf);
            }
        }

        // ---- causal mask on (partially) diagonal tiles ----
        if (jt >= 2 * qt) {
            int row0 = qt * 128 + w * 16 + g;
            int row1 = row0 + 8;
#pragma unroll
            for (int j = 0; j < 8; j++) {
                int col = jt * 64 + j * 8 + 2 * tig;
                if (col     > row0) Sacc[j][0] = -1e30f;
                if (col + 1 > row0) Sacc[j][1] = -1e30f;
                if (col     > row1) Sacc[j][2] = -1e30f;
                if (col + 1 > row1) Sacc[j][3] = -1e30f;
            }
        }

        // ---- online softmax (rows g and g+8) ----
#pragma unroll
        for (int r = 0; r < 2; r++) {
            const int c0 = 2 * r;
            float mx = Sacc[0][c0];
#pragma unroll
            for (int j = 0; j < 8; j++) {
                mx = fmaxf(mx, Sacc[j][c0]);
                mx = fmaxf(mx, Sacc[j][c0 + 1]);
            }
            mx = fmaxf(mx, __shfl_xor_sync(0xffffffffu, mx, 1));
            mx = fmaxf(mx, __shfl_xor_sync(0xffffffffu, mx, 2));
            float mnew  = fmaxf(rmax[r], mx);
            float scale = __expf(rmax[r] - mnew);
            rmax[r] = mnew;
            float s = 0.f;
#pragma unroll
            for (int j = 0; j < 8; j++) {
                Sacc[j][c0]     = __expf(Sacc[j][c0]     - mnew);
                Sacc[j][c0 + 1] = __expf(Sacc[j][c0 + 1] - mnew);
                s += Sacc[j][c0] + Sacc[j][c0 + 1];
            }
            s += __shfl_xor_sync(0xffffffffu, s, 1);
            s += __shfl_xor_sync(0xffffffffu, s, 2);
            rsum[r] = rsum[r] * scale + s;
#pragma unroll
            for (int j = 0; j < 8; j++) {
                Oacc[j][c0]     *= scale;
                Oacc[j][c0 + 1] *= scale;
            }
        }

        // ---- P -> bf16 hi/lo smem (own rows; cols 2tig,2tig+1 pack) ----
#pragma unroll
        for (int j = 0; j < 8; j++) {
            uint32_t h0, l0, h1, l1;
            split_pack(Sacc[j][0], Sacc[j][1], h0, l0);
            split_pack(Sacc[j][2], Sacc[j][3], h1, l1);
            int o0 = (w * 16 + g) * QST + j * 8 + 2 * tig;
            int o1 = (w * 16 + g + 8) * QST + j * 8 + 2 * tig;
            *(uint32_t*)(Phi + o0) = h0;
            *(uint32_t*)(Plo + o0) = l0;
            *(uint32_t*)(Phi + o1) = h1;
            *(uint32_t*)(Plo + o1) = l1;
        }
        __syncwarp();

        // ---- O += P @ V (3-pass 2-plane bf16, k16 over 64 keys) ----
#pragma unroll
        for (int kf = 0; kf < 4; kf++) {
            const int kc = kf * 16 + 2 * tig;
            int ab = (w * 16 + g) * QST + kc;
            uint32_t ph[4], pl[4];
            ph[0] = *(const uint32_t*)(Phi + ab);
            ph[1] = *(const uint32_t*)(Phi + ab + 8 * QST);
            ph[2] = *(const uint32_t*)(Phi + ab + 8);
            ph[3] = *(const uint32_t*)(Phi + ab + 8 * QST + 8);
            pl[0] = *(const uint32_t*)(Plo + ab);
            pl[1] = *(const uint32_t*)(Plo + ab + 8 * QST);
            pl[2] = *(const uint32_t*)(Plo + ab + 8);
            pl[3] = *(const uint32_t*)(Plo + ab + 8 * QST + 8);
#pragma unroll
            for (int j = 0; j < 8; j++) {
                int bb = (j * 8 + g) * QST + kc;
                uint32_t vhf[2] = {*(const uint32_t*)(Vhi + bb), *(const uint32_t*)(Vhi + bb + 8)};
                uint32_t vlf[2] = {*(const uint32_t*)(Vlo + bb), *(const uint32_t*)(Vlo + bb + 8)};
                mma_bf16(Oacc[j], ph, vhf);
                mma_bf16(Oacc[j], ph, vlf);
                mma_bf16(Oacc[j], pl, vhf);
            }
        }
    }

    // ---- epilogue: normalize, split, write bf16 planes for O-projection ----
    {
        float inv0 = 1.0f / rsum[0];
        float inv1 = 1.0f / rsum[1];
        int row0 = qt * 128 + w * 16 + g;
        int row1 = row0 + 8;
#pragma unroll
        for (int j = 0; j < 8; j++) {
            int col = j * 8 + 2 * tig;
            uint32_t h0, l0, h1, l1;
            split_pack(Oacc[j][0] * inv0, Oacc[j][1] * inv0, h0, l0);
            split_pack(Oacc[j][2] * inv1, Oacc[j][3] * inv1, h1, l1);
            size_t ofs0 = base + (size_t)row0 * DM + col;
            size_t ofs1 = base + (size_t)row1 * DM + col;
            *(uint32_t*)(g_Ab0 + ofs0) = h0;
            *(uint32_t*)(g_Ab1 + ofs0) = l0;
            *(uint32_t*)(g_Ab0 + ofs1) = h1;
            *(uint32_t*)(g_Ab1 + ofs1) = l1;
        }
    }
}

// ---------------------------------------------------------------------------
extern "C" void kernel_launch(void* const* d_in, const int* in_sizes, int n_in,
                              void* d_out, int out_size)
{
    const float* x = 0;
    const float* Ws[4] = {0, 0, 0, 0};
    const float* bs[4] = {0, 0, 0, 0};
    int nw = 0, nb = 0;
    for (int i = 0; i < n_in; i++) {
        if (in_sizes[i] == M_TOT * DM)      x = (const float*)d_in[i];
        else if (in_sizes[i] == DM * DM)    { if (nw < 4) Ws[nw++] = (const float*)d_in[i]; }
        else if (in_sizes[i] == DM)         { if (nb < 4) bs[nb++] = (const float*)d_in[i]; }
    }
    const float *bq = bs[0], *bk = bs[1], *bv = bs[2], *bo = bs[3];
    float* out = (float*)d_out;

    void *pxb0, *pxb1, *pWb0, *pWb1;
    void *pQb0, *pQb1, *pKb0, *pKb1, *pVb0, *pVb1, *pAb0, *pAb1;
    cudaGetSymbolAddress(&pxb0, g_xb0); cudaGetSymbolAddress(&pxb1, g_xb1);
    cudaGetSymbolAddress(&pWb0, g_Wb0); cudaGetSymbolAddress(&pWb1, g_Wb1);
    cudaGetSymbolAddress(&pQb0, g_Qb0); cudaGetSymbolAddress(&pQb1, g_Qb1);
    cudaGetSymbolAddress(&pKb0, g_Kb0); cudaGetSymbolAddress(&pKb1, g_Kb1);
    cudaGetSymbolAddress(&pVb0, g_Vb0); cudaGetSymbolAddress(&pVb1, g_Vb1);
    cudaGetSymbolAddress(&pAb0, g_Ab0); cudaGetSymbolAddress(&pAb1, g_Ab1);

    // 0) split x (one launch) and all four weights (one z=4 launch)
    split2_kernel<<<4096, 256>>>(x, (__nv_bfloat16*)pxb0, (__nv_bfloat16*)pxb1, M_TOT * DM);
    split2w_kernel<<<dim3(512, 1, 4), 256>>>(Ws[0], Ws[1], Ws[2], Ws[3],
                                             (__nv_bfloat16*)pWb0, (__nv_bfloat16*)pWb1);

    cudaFuncSetAttribute(gemm_bf16_kernel, cudaFuncAttributeMaxDynamicSharedMemorySize, GEMM_SMEM);

    // 1) Fused Q/K/V projections -> bf16 planes (Q prescaled by 1/8)
    gemm_bf16_kernel<<<dim3(M_TOT / GBM, DM / GBN, 3), 256, GEMM_SMEM>>>(
        (const __nv_bfloat16*)pxb0, (const __nv_bfloat16*)pxb1,
        (const __nv_bfloat16*)pWb0, (const __nv_bfloat16*)pWb1, 0, /*plane_mode=*/1,
        bq, bk, bv, nullptr,
        (__nv_bfloat16*)pQb0, (__nv_bfloat16*)pQb1,
        (__nv_bfloat16*)pKb0, (__nv_bfloat16*)pKb1,
        (__nv_bfloat16*)pVb0, (__nv_bfloat16*)pVb1);

    // 2) Causal flash attention v6 (pipelined) -> g_Ab planes
    cudaFuncSetAttribute(attn_kernel, cudaFuncAttributeMaxDynamicSharedMemorySize, ATTN_SMEM);
    attn_kernel<<<dim3(SEQ / 128, 4 * N_HEADS), 256, ATTN_SMEM>>>();

    // 3) O-projection (weight slice 3) -> fp32 d_out
    gemm_bf16_kernel<<<dim3(M_TOT / GBM, DM / GBN, 1), 256, GEMM_SMEM>>>(
        (const __nv_bfloat16*)pAb0, (const __nv_bfloat16*)pAb1,
        (const __nv_bfloat16*)pWb0, (const __nv_bfloat16*)pWb1, 3, /*plane_mode=*/0,
        bo, bo, bo, out,
        nullptr, nullptr, nullptr, nullptr, nullptr, nullptr);
}